// round 17
// baseline (speedup 1.0000x reference)
#include <cuda_runtime.h>
#include <cstdint>

#define IN_F   8192
#define OUT_F  8192
#define THR    50.0f
#define NT     256
#define NV     (IN_F / 4)         // 2048 float4 per row
#define FPT    (NV / NT)          // 8 float4 per thread per row
#define HALF   (FPT / 2)          // rolling elig pipeline granularity

__global__ __launch_bounds__(NT)
void snn_row2_kernel(const float* __restrict__ x,
                     const float* __restrict__ syn,
                     const float* __restrict__ mp,
                     const float* __restrict__ thr,
                     const float* __restrict__ elig,
                     float* __restrict__ out) {
    __shared__ float red[2][NT / 32];
    const int t  = threadIdx.x;
    const int r0 = blockIdx.x * 2;
    const int r1 = r0 + 1;

    const float4* x4  = reinterpret_cast<const float4*>(x);  // 32 KB, L1-resident
    const float4* sa4 = reinterpret_cast<const float4*>(syn  + (size_t)r0 * IN_F);
    const float4* sb4 = reinterpret_cast<const float4*>(syn  + (size_t)r1 * IN_F);
    const float4* ea4 = reinterpret_cast<const float4*>(elig + (size_t)r0 * IN_F);
    const float4* eb4 = reinterpret_cast<const float4*>(elig + (size_t)r1 * IN_F);

    // ── Phase 1, row 0 ──
    float4 s[FPT];
    #pragma unroll
    for (int j = 0; j < FPT; j++)
        s[j] = __ldcs(&sa4[t + j * NT]);         // 8 LDG.128 in flight

    float a0 = 0.0f, a1 = 0.0f, a2 = 0.0f, a3 = 0.0f;
    #pragma unroll
    for (int j = 0; j < FPT; j++) {
        float4 xv = __ldg(&x4[t + j * NT]);
        a0 += (s[j].x > THR ? xv.x : 0.0f);
        a1 += (s[j].y > THR ? xv.y : 0.0f);
        a2 += (s[j].z > THR ? xv.z : 0.0f);
        a3 += (s[j].w > THR ? xv.w : 0.0f);
    }
    float accA = (a0 + a1) + (a2 + a3);

    // ── Phase 1, row 1 (s[] registers reused) ──
    #pragma unroll
    for (int j = 0; j < FPT; j++)
        s[j] = __ldcs(&sb4[t + j * NT]);

    float b0 = 0.0f, b1 = 0.0f, b2 = 0.0f, b3 = 0.0f;
    #pragma unroll
    for (int j = 0; j < FPT; j++) {
        float4 xv = __ldg(&x4[t + j * NT]);
        b0 += (s[j].x > THR ? xv.x : 0.0f);
        b1 += (s[j].y > THR ? xv.y : 0.0f);
        b2 += (s[j].z > THR ? xv.z : 0.0f);
        b3 += (s[j].w > THR ? xv.w : 0.0f);
    }
    float accB = (b0 + b1) + (b2 + b3);

    // Start the rolling elig pipeline: row0 first half in flight across barrier
    float4 e[HALF];
    #pragma unroll
    for (int j = 0; j < HALF; j++)
        e[j] = __ldcs(&ea4[t + j * NT]);

    // ── One barrier for both rows ──
    #pragma unroll
    for (int off = 16; off > 0; off >>= 1) {
        accA += __shfl_down_sync(0xffffffffu, accA, off);
        accB += __shfl_down_sync(0xffffffffu, accB, off);
    }
    if ((t & 31) == 0) {
        red[0][t >> 5] = accA;
        red[1][t >> 5] = accB;
    }
    __syncthreads();

    // Issue row0 second half immediately post-barrier
    float4 e2[HALF];
    #pragma unroll
    for (int j = 0; j < HALF; j++)
        e2[j] = __ldcs(&ea4[t + (HALF + j) * NT]);

    float curA = 0.0f, curB = 0.0f;
    #pragma unroll
    for (int w = 0; w < NT / 32; w++) { curA += red[0][w]; curB += red[1][w]; }
    const float vA  = __ldg(mp + r0) * 0.6f + curA;
    const float vB  = __ldg(mp + r1) * 0.6f + curB;
    const float spA = (vA >= __ldg(thr + r0)) ? 1.0f : 0.0f;
    const float spB = (vB >= __ldg(thr + r1)) ? 1.0f : 0.0f;
    if (t == 0) {
        out[r0] = spA;
        out[r1] = spB;
        out[OUT_F + r0] = vA * (1.0f - spA) * 0.3f;
        out[OUT_F + r1] = vB * (1.0f - spB) * 0.3f;
    }

    // ── Phase 2: rolling pipeline across both rows ──
    float4* oa4 = reinterpret_cast<float4*>(out + 2 * (size_t)OUT_F + (size_t)r0 * IN_F);
    float4* ob4 = reinterpret_cast<float4*>(out + 2 * (size_t)OUT_F + (size_t)r1 * IN_F);

    // consume e (row0 h1) while e2 (row0 h2) in flight; issue row1 h1 into e
    float4 e3[HALF];
    #pragma unroll
    for (int j = 0; j < HALF; j++)
        e3[j] = __ldcs(&eb4[t + j * NT]);        // row1 first half in flight
    #pragma unroll
    for (int j = 0; j < HALF; j++) {
        float4 xv = __ldg(&x4[t + j * NT]);
        float4 r;
        r.x = fminf(fmaxf(fmaf(e[j].x, 0.7f, spA * xv.x), 0.0f), 3.0f);
        r.y = fminf(fmaxf(fmaf(e[j].y, 0.7f, spA * xv.y), 0.0f), 3.0f);
        r.z = fminf(fmaxf(fmaf(e[j].z, 0.7f, spA * xv.z), 0.0f), 3.0f);
        r.w = fminf(fmaxf(fmaf(e[j].w, 0.7f, spA * xv.w), 0.0f), 3.0f);
        __stcs(&oa4[t + j * NT], r);
    }

    // consume e2 (row0 h2); issue row1 h2 into e (reused)
    #pragma unroll
    for (int j = 0; j < HALF; j++)
        e[j] = __ldcs(&eb4[t + (HALF + j) * NT]);
    #pragma unroll
    for (int j = 0; j < HALF; j++) {
        float4 xv = __ldg(&x4[t + (HALF + j) * NT]);
        float4 r;
        r.x = fminf(fmaxf(fmaf(e2[j].x, 0.7f, spA * xv.x), 0.0f), 3.0f);
        r.y = fminf(fmaxf(fmaf(e2[j].y, 0.7f, spA * xv.y), 0.0f), 3.0f);
        r.z = fminf(fmaxf(fmaf(e2[j].z, 0.7f, spA * xv.z), 0.0f), 3.0f);
        r.w = fminf(fmaxf(fmaf(e2[j].w, 0.7f, spA * xv.w), 0.0f), 3.0f);
        __stcs(&oa4[t + (HALF + j) * NT], r);
    }

    // consume e3 (row1 h1)
    #pragma unroll
    for (int j = 0; j < HALF; j++) {
        float4 xv = __ldg(&x4[t + j * NT]);
        float4 r;
        r.x = fminf(fmaxf(fmaf(e3[j].x, 0.7f, spB * xv.x), 0.0f), 3.0f);
        r.y = fminf(fmaxf(fmaf(e3[j].y, 0.7f, spB * xv.y), 0.0f), 3.0f);
        r.z = fminf(fmaxf(fmaf(e3[j].z, 0.7f, spB * xv.z), 0.0f), 3.0f);
        r.w = fminf(fmaxf(fmaf(e3[j].w, 0.7f, spB * xv.w), 0.0f), 3.0f);
        __stcs(&ob4[t + j * NT], r);
    }

    // consume e (row1 h2)
    #pragma unroll
    for (int j = 0; j < HALF; j++) {
        float4 xv = __ldg(&x4[t + (HALF + j) * NT]);
        float4 r;
        r.x = fminf(fmaxf(fmaf(e[j].x, 0.7f, spB * xv.x), 0.0f), 3.0f);
        r.y = fminf(fmaxf(fmaf(e[j].y, 0.7f, spB * xv.y), 0.0f), 3.0f);
        r.z = fminf(fmaxf(fmaf(e[j].z, 0.7f, spB * xv.z), 0.0f), 3.0f);
        r.w = fminf(fmaxf(fmaf(e[j].w, 0.7f, spB * xv.w), 0.0f), 3.0f);
        __stcs(&ob4[t + (HALF + j) * NT], r);
    }
}

extern "C" void kernel_launch(void* const* d_in, const int* in_sizes, int n_in,
                              void* d_out, int out_size) {
    const float* x    = (const float*)d_in[0];  // spike_input [1, 8192]
    const float* syn  = (const float*)d_in[1];  // synapse_states [8192, 8192]
    const float* mp   = (const float*)d_in[2];  // membrane_potential [8192]
    const float* thr  = (const float*)d_in[3];  // adaptive_threshold [8192]
    const float* elig = (const float*)d_in[4];  // eligibility_trace [8192, 8192]
    float* out = (float*)d_out;                 // [spikes | v_new | trace_new]

    snn_row2_kernel<<<OUT_F / 2, NT>>>(x, syn, mp, thr, elig, out);
}